// round 5
// baseline (speedup 1.0000x reference)
#include <cuda_runtime.h>
#include <cstdint>

#define N_NODES  50000
#define N_GRAPHS 128
#define HID      512
#define QELEMS   (N_GRAPHS * HID)
#define NWALK    12
#define NCHUNK   74
#define CHUNK    676          // 74*676 = 50024 >= 50000
#define TILE     64
#define CAP      48           // max distinct graphs kept per node (P(overflow) ~ 1e-9)

// ---------------- device scratch ----------------
__device__ unsigned g_A8[N_NODES * 32];   // packed byte counts: A8[j][g], 4 g per word
__device__ int      g_pb[N_NODES];
__device__ int      g_counts[N_GRAPHS];
__device__ float    g_Q[QELEMS];
__device__ float    g_R0[QELEMS];
__device__ float    g_R1[QELEMS];
__device__ float    g_R2[QELEMS];
__device__ float    g_P0[QELEMS];
__device__ float    g_P1[QELEMS];

// ---------------- zero scratch ----------------
__global__ void k_zero() {
    unsigned i = blockIdx.x * blockDim.x + threadIdx.x;
    uint4 z = make_uint4(0, 0, 0, 0);
    if (i < 400000u) ((uint4*)g_A8)[i] = z;          // 6.4 MB
    if (i < 16384u) {
        ((uint4*)g_Q)[i]  = z;
        ((uint4*)g_R0)[i] = z;
        ((uint4*)g_R1)[i] = z;
        ((uint4*)g_R2)[i] = z;
    }
    if (i < N_GRAPHS) g_counts[i] = 0;
}

// ---------------- path_batch + per-graph node counts ----------------
__global__ void k_pb(const int* __restrict__ walk2, const int* __restrict__ batch) {
    int n = blockIdx.x * blockDim.x + threadIdx.x;
    if (n < N_NODES) {
        int g = batch[walk2[n]];      // walk2 row 0
        g_pb[n] = g;
        atomicAdd(&g_counts[g], 1);
    }
}

// ---------------- build packed count matrix A8[j][g] ----------------
__global__ void k_a8(const int* __restrict__ w2, const int* __restrict__ w3,
                     const int* __restrict__ w4) {
    int e = blockIdx.x * blockDim.x + threadIdx.x;
    if (e >= NWALK * N_NODES) return;
    int j, n;
    if (e < 3 * N_NODES)      { j = w2[e];               n = e % N_NODES; }
    else if (e < 7 * N_NODES) { int t = e - 3 * N_NODES; j = w3[t]; n = t % N_NODES; }
    else                      { int t = e - 7 * N_NODES; j = w4[t]; n = t % N_NODES; }
    int g = g_pb[n];
    atomicAdd(&g_A8[j * 32 + (g >> 2)], 1u << ((g & 3) * 8));
}

// ---------------- main: Q = A @ x, j-major scatter ----------------
// grid (2 g-halves, NCHUNK), 256 threads.
// Each warp owns a 64-col slice and a private 64g x 64c fp32 accumulator (16KB).
__global__ __launch_bounds__(256, 1)
void k_main(const float* __restrict__ x) {
    extern __shared__ unsigned char dsm[];            // 8 * 16384 = 128 KB acc
    __shared__ unsigned short s_gl[TILE * CAP];       // (g_local | count<<8) per node
    __shared__ int s_cnt[TILE];

    const int ghalf = blockIdx.x;
    const int chunk = blockIdx.y;
    const int tid   = threadIdx.x;
    const int wid   = tid >> 5;
    const int lane  = tid & 31;

    // zero acc (128 KB)
    float4* acc4 = (float4*)dsm;
    #pragma unroll
    for (int i = 0; i < 32; i++) acc4[tid + i * 256] = make_float4(0.f, 0.f, 0.f, 0.f);
    __syncthreads();

    const int j0 = chunk * CHUNK;
    const int j1 = (j0 + CHUNK < N_NODES) ? j0 + CHUNK : N_NODES;

    float* wacc = (float*)(dsm + wid * 16384);        // [g][64 floats]

    for (int jt = j0; jt < j1; jt += TILE) {
        const int tn = (jt + TILE <= j1) ? TILE : (j1 - jt);

        // ---- decode phase: warp-per-node, A8 half-row -> (g,c) list ----
        for (int t = wid; t < tn; t += 8) {
            int j = jt + t;
            unsigned w = (lane < 16) ? g_A8[j * 32 + ghalf * 16 + lane] : 0u;
            int c0 = (int)((w & 0x000000FFu) != 0) + (int)((w & 0x0000FF00u) != 0)
                   + (int)((w & 0x00FF0000u) != 0) + (int)((w & 0xFF000000u) != 0);
            int v = c0;
            #pragma unroll
            for (int d = 1; d < 32; d <<= 1) {
                int u = __shfl_up_sync(0xFFFFFFFFu, v, d);
                if (lane >= d) v += u;
            }
            int pos   = v - c0;
            int total = __shfl_sync(0xFFFFFFFFu, v, 31);
            if (lane == 0) s_cnt[t] = (total < CAP) ? total : CAP;
            int p = pos;
            #pragma unroll
            for (int b = 0; b < 4; b++) {
                unsigned byte = (w >> (8 * b)) & 255u;
                if (byte && p < CAP) {
                    s_gl[t * CAP + p] = (unsigned short)((unsigned)(lane * 4 + b) | (byte << 8));
                    p++;
                }
            }
        }
        __syncthreads();

        // ---- accumulate phase: every warp, its 64-col slice, all tile nodes ----
        for (int t = 0; t < tn; t++) {
            int j = jt + t;
            float2 v = *(const float2*)(x + j * HID + wid * 64 + lane * 2);
            int cnt = s_cnt[t];
            for (int base = 0; base < cnt; base += 16) {
                float ox[16], oy[16], cm[16];
                int   ga[16];
                // batched loads (distinct g within a node => no intra-batch alias)
                #pragma unroll
                for (int i = 0; i < 16; i++) {
                    if (base + i < cnt) {
                        unsigned short e = s_gl[t * CAP + base + i];
                        ga[i] = (int)(e & 255u) * 64 + lane * 2;
                        cm[i] = (float)(e >> 8);
                        ox[i] = wacc[ga[i]];
                        oy[i] = wacc[ga[i] + 1];
                    }
                }
                #pragma unroll
                for (int i = 0; i < 16; i++) {
                    if (base + i < cnt) {
                        wacc[ga[i]]     = fmaf(v.x, cm[i], ox[i]);
                        wacc[ga[i] + 1] = fmaf(v.y, cm[i], oy[i]);
                    }
                }
            }
        }
        __syncthreads();
    }

    // ---- flush: warp-private acc -> global Q (atomic across chunks) ----
    #pragma unroll 4
    for (int g = 0; g < 64; g++) {
        float a0 = wacc[g * 64 + lane * 2];
        float a1 = wacc[g * 64 + lane * 2 + 1];
        int gg = ghalf * 64 + g;
        atomicAdd(&g_Q[gg * HID + wid * 64 + lane * 2],     a0);
        atomicAdd(&g_Q[gg * HID + wid * 64 + lane * 2 + 1], a1);
    }
}

// ---------------- small GEMM: R += A[128,512] @ W[512,512], split-K ----------------
#define GK 32
#define GN 64
__global__ __launch_bounds__(256)
void k_gemm(const float* __restrict__ A, const float* __restrict__ W,
            float* __restrict__ R) {
    __shared__ float sA[GK][129];
    __shared__ float sB[GK][GN];
    int nb = blockIdx.x;
    int kb = blockIdx.y;
    int tid = threadIdx.x;

    for (int i = tid; i < 128 * GK; i += 256) {
        int m = i >> 5;
        int k = i & 31;
        sA[k][m] = A[m * HID + kb * GK + k];
    }
    for (int i = tid; i < GK * GN; i += 256) {
        int k = i >> 6;
        int cc = i & 63;
        sB[k][cc] = W[(kb * GK + k) * HID + nb * GN + cc];
    }
    __syncthreads();

    int trow = tid >> 4;
    int tcol = tid & 15;
    float acc[8][4];
    #pragma unroll
    for (int i = 0; i < 8; i++)
        #pragma unroll
        for (int jj = 0; jj < 4; jj++) acc[i][jj] = 0.f;

    #pragma unroll
    for (int k = 0; k < GK; k++) {
        float a[8], b[4];
        #pragma unroll
        for (int i = 0; i < 8; i++) a[i] = sA[k][trow * 8 + i];
        #pragma unroll
        for (int jj = 0; jj < 4; jj++) b[jj] = sB[k][tcol * 4 + jj];
        #pragma unroll
        for (int i = 0; i < 8; i++)
            #pragma unroll
            for (int jj = 0; jj < 4; jj++) acc[i][jj] += a[i] * b[jj];
    }

    #pragma unroll
    for (int i = 0; i < 8; i++)
        #pragma unroll
        for (int jj = 0; jj < 4; jj++)
            atomicAdd(&R[(trow * 8 + i) * HID + nb * GN + tcol * 4 + jj], acc[i][jj]);
}

// ---------------- epilogue: P = R + 12*cnt*b ; out = P / max(cnt,1) ----------------
__global__ void k_epi(const float* __restrict__ R, const float* __restrict__ bias,
                      float* __restrict__ Pout, float* __restrict__ out, int layer) {
    int i = blockIdx.x * blockDim.x + threadIdx.x;
    if (i < QELEMS) {
        int m = i >> 9;
        int c = i & 511;
        float cnt = (float)g_counts[m];
        float v = R[i] + 12.0f * cnt * bias[c];
        if (Pout) Pout[i] = v;
        out[m * (3 * HID) + layer * HID + c] = v / fmaxf(cnt, 1.0f);
    }
}

// ---------------- launch ----------------
extern "C" void kernel_launch(void* const* d_in, const int* in_sizes, int n_in,
                              void* d_out, int out_size) {
    const float* x     = (const float*)d_in[0];
    const int*   walk2 = (const int*)  d_in[1];
    const int*   walk3 = (const int*)  d_in[2];
    const int*   walk4 = (const int*)  d_in[3];
    const int*   batch = (const int*)  d_in[4];
    const float* W0 = (const float*)d_in[5];
    const float* b0 = (const float*)d_in[6];
    const float* W1 = (const float*)d_in[7];
    const float* b1 = (const float*)d_in[8];
    const float* W2 = (const float*)d_in[9];
    const float* b2 = (const float*)d_in[10];
    float* out = (float*)d_out;

    float *pQ, *pR0, *pR1, *pR2, *pP0, *pP1;
    cudaGetSymbolAddress((void**)&pQ,  g_Q);
    cudaGetSymbolAddress((void**)&pR0, g_R0);
    cudaGetSymbolAddress((void**)&pR1, g_R1);
    cudaGetSymbolAddress((void**)&pR2, g_R2);
    cudaGetSymbolAddress((void**)&pP0, g_P0);
    cudaGetSymbolAddress((void**)&pP1, g_P1);

    cudaFuncSetAttribute(k_main, cudaFuncAttributeMaxDynamicSharedMemorySize, 131072);

    k_zero<<<1563, 256>>>();                                     // covers 400128 uint4
    k_pb<<<(N_NODES + 255) / 256, 256>>>(walk2, batch);
    k_a8<<<(NWALK * N_NODES + 255) / 256, 256>>>(walk2, walk3, walk4);
    k_main<<<dim3(2, NCHUNK), 256, 131072>>>(x);

    k_gemm<<<dim3(8, 16), 256>>>(pQ, W0, pR0);
    k_epi<<<(QELEMS + 255) / 256, 256>>>(pR0, b0, pP0, out, 0);

    k_gemm<<<dim3(8, 16), 256>>>(pP0, W1, pR1);
    k_epi<<<(QELEMS + 255) / 256, 256>>>(pR1, b1, pP1, out, 1);

    k_gemm<<<dim3(8, 16), 256>>>(pP1, W2, pR2);
    k_epi<<<(QELEMS + 255) / 256, 256>>>(pR2, b2, nullptr, out, 2);
}

// round 6
// speedup vs baseline: 2.7446x; 2.7446x over previous
#include <cuda_runtime.h>
#include <cstdint>

#define N_NODES  50000
#define N_GRAPHS 128
#define HID      512
#define QELEMS   (N_GRAPHS * HID)
#define NWALK    12
#define NENT     (N_NODES * NWALK)
#define NSLICE   8

// ---------------- device scratch ----------------
__device__ int   g_pb[N_NODES];
__device__ int   g_counts[N_GRAPHS];
__device__ int   g_cursors[N_GRAPHS];
__device__ int   g_off12[N_GRAPHS];      // 12 * exclusive-scan(counts)
__device__ int   g_ent[NENT];            // per-graph contiguous target-j lists
__device__ float g_Q[QELEMS];
__device__ float g_R0[QELEMS];
__device__ float g_R1[QELEMS];
__device__ float g_R2[QELEMS];
__device__ float g_P0[QELEMS];
__device__ float g_P1[QELEMS];

// ---------------- zero scratch ----------------
__global__ void k_zero() {
    int i = blockIdx.x * blockDim.x + threadIdx.x;
    uint4 z = make_uint4(0, 0, 0, 0);
    if (i < 16384) {
        ((uint4*)g_Q)[i]  = z;
        ((uint4*)g_R0)[i] = z;
        ((uint4*)g_R1)[i] = z;
        ((uint4*)g_R2)[i] = z;
    }
    if (i < N_GRAPHS) { g_counts[i] = 0; g_cursors[i] = 0; }
}

// ---------------- path_batch + histogram ----------------
__global__ void k_pb(const int* __restrict__ walk2, const int* __restrict__ batch) {
    int n = blockIdx.x * blockDim.x + threadIdx.x;
    if (n < N_NODES) {
        int g = batch[walk2[n]];   // walk2 row 0
        g_pb[n] = g;
        atomicAdd(&g_counts[g], 1);
    }
}

// ---------------- parallel exclusive scan over 128 counts ----------------
__global__ void k_scan() {
    __shared__ int s[N_GRAPHS];
    int t = threadIdx.x;
    int v = g_counts[t];
    s[t] = v;
    __syncthreads();
    #pragma unroll
    for (int d = 1; d < N_GRAPHS; d <<= 1) {
        int u = (t >= d) ? s[t - d] : 0;
        __syncthreads();
        s[t] += u;
        __syncthreads();
    }
    g_off12[t] = (s[t] - v) * NWALK;
}

// ---------------- build per-graph contiguous entry lists ----------------
__global__ void k_build(const int* __restrict__ w2, const int* __restrict__ w3,
                        const int* __restrict__ w4) {
    int n = blockIdx.x * blockDim.x + threadIdx.x;
    if (n >= N_NODES) return;
    int g = g_pb[n];
    int base = g_off12[g] + atomicAdd(&g_cursors[g], NWALK);
    g_ent[base + 0]  = w2[n];
    g_ent[base + 1]  = w2[N_NODES + n];
    g_ent[base + 2]  = w2[2 * N_NODES + n];
    g_ent[base + 3]  = w3[n];
    g_ent[base + 4]  = w3[N_NODES + n];
    g_ent[base + 5]  = w3[2 * N_NODES + n];
    g_ent[base + 6]  = w3[3 * N_NODES + n];
    g_ent[base + 7]  = w4[n];
    g_ent[base + 8]  = w4[N_NODES + n];
    g_ent[base + 9]  = w4[2 * N_NODES + n];
    g_ent[base + 10] = w4[3 * N_NODES + n];
    g_ent[base + 11] = w4[4 * N_NODES + n];
}

// ---------------- Q = A @ x : streaming gather ----------------
// grid (N_GRAPHS, NSLICE), 128 threads; thread owns 4 cols (one float4).
__global__ __launch_bounds__(128)
void k_gather(const float* __restrict__ x) {
    const int g  = blockIdx.x;
    const int sl = blockIdx.y;
    const int start = g_off12[g];
    const int len   = g_counts[g] * NWALK;
    int e  = start + (len * sl) / NSLICE;
    const int s1 = start + (len * (sl + 1)) / NSLICE;

    const float4* __restrict__ x4 = (const float4*)x;
    const int c = threadIdx.x;
    float4 acc = make_float4(0.f, 0.f, 0.f, 0.f);

    for (; e + 4 <= s1; e += 4) {
        int j0 = __ldg(&g_ent[e]);
        int j1 = __ldg(&g_ent[e + 1]);
        int j2 = __ldg(&g_ent[e + 2]);
        int j3 = __ldg(&g_ent[e + 3]);
        float4 v0 = x4[j0 * 128 + c];
        float4 v1 = x4[j1 * 128 + c];
        float4 v2 = x4[j2 * 128 + c];
        float4 v3 = x4[j3 * 128 + c];
        acc.x += (v0.x + v1.x) + (v2.x + v3.x);
        acc.y += (v0.y + v1.y) + (v2.y + v3.y);
        acc.z += (v0.z + v1.z) + (v2.z + v3.z);
        acc.w += (v0.w + v1.w) + (v2.w + v3.w);
    }
    for (; e < s1; ++e) {
        int j = __ldg(&g_ent[e]);
        float4 v = x4[j * 128 + c];
        acc.x += v.x; acc.y += v.y; acc.z += v.z; acc.w += v.w;
    }

    float* Qrow = &g_Q[g * HID + 4 * c];
    atomicAdd(Qrow + 0, acc.x);
    atomicAdd(Qrow + 1, acc.y);
    atomicAdd(Qrow + 2, acc.z);
    atomicAdd(Qrow + 3, acc.w);
}

// ---------------- small GEMM: R += A[128,512] @ W[512,512], split-K ----------------
#define GK 32
#define GN 64
__global__ __launch_bounds__(256)
void k_gemm(const float* __restrict__ A, const float* __restrict__ W,
            float* __restrict__ R) {
    __shared__ float sA[GK][129];
    __shared__ float sB[GK][GN];
    int nb = blockIdx.x;
    int kb = blockIdx.y;
    int tid = threadIdx.x;

    for (int i = tid; i < 128 * GK; i += 256) {
        int m = i >> 5;
        int k = i & 31;
        sA[k][m] = A[m * HID + kb * GK + k];
    }
    for (int i = tid; i < GK * GN; i += 256) {
        int k = i >> 6;
        int cc = i & 63;
        sB[k][cc] = W[(kb * GK + k) * HID + nb * GN + cc];
    }
    __syncthreads();

    int trow = tid >> 4;
    int tcol = tid & 15;
    float acc[8][4];
    #pragma unroll
    for (int i = 0; i < 8; i++)
        #pragma unroll
        for (int jj = 0; jj < 4; jj++) acc[i][jj] = 0.f;

    #pragma unroll
    for (int k = 0; k < GK; k++) {
        float a[8], b[4];
        #pragma unroll
        for (int i = 0; i < 8; i++) a[i] = sA[k][trow * 8 + i];
        #pragma unroll
        for (int jj = 0; jj < 4; jj++) b[jj] = sB[k][tcol * 4 + jj];
        #pragma unroll
        for (int i = 0; i < 8; i++)
            #pragma unroll
            for (int jj = 0; jj < 4; jj++) acc[i][jj] += a[i] * b[jj];
    }

    #pragma unroll
    for (int i = 0; i < 8; i++)
        #pragma unroll
        for (int jj = 0; jj < 4; jj++)
            atomicAdd(&R[(trow * 8 + i) * HID + nb * GN + tcol * 4 + jj], acc[i][jj]);
}

// ---------------- epilogue: P = R + 12*cnt*b ; out = P / max(cnt,1) ----------------
__global__ void k_epi(const float* __restrict__ R, const float* __restrict__ bias,
                      float* __restrict__ Pout, float* __restrict__ out, int layer) {
    int i = blockIdx.x * blockDim.x + threadIdx.x;
    if (i < QELEMS) {
        int m = i >> 9;
        int c = i & 511;
        float cnt = (float)g_counts[m];
        float v = R[i] + 12.0f * cnt * bias[c];
        if (Pout) Pout[i] = v;
        out[m * (3 * HID) + layer * HID + c] = v / fmaxf(cnt, 1.0f);
    }
}

// ---------------- launch ----------------
extern "C" void kernel_launch(void* const* d_in, const int* in_sizes, int n_in,
                              void* d_out, int out_size) {
    const float* x     = (const float*)d_in[0];
    const int*   walk2 = (const int*)  d_in[1];
    const int*   walk3 = (const int*)  d_in[2];
    const int*   walk4 = (const int*)  d_in[3];
    const int*   batch = (const int*)  d_in[4];
    const float* W0 = (const float*)d_in[5];
    const float* b0 = (const float*)d_in[6];
    const float* W1 = (const float*)d_in[7];
    const float* b1 = (const float*)d_in[8];
    const float* W2 = (const float*)d_in[9];
    const float* b2 = (const float*)d_in[10];
    float* out = (float*)d_out;

    float *pQ, *pR0, *pR1, *pR2, *pP0, *pP1;
    cudaGetSymbolAddress((void**)&pQ,  g_Q);
    cudaGetSymbolAddress((void**)&pR0, g_R0);
    cudaGetSymbolAddress((void**)&pR1, g_R1);
    cudaGetSymbolAddress((void**)&pR2, g_R2);
    cudaGetSymbolAddress((void**)&pP0, g_P0);
    cudaGetSymbolAddress((void**)&pP1, g_P1);

    k_zero<<<64, 256>>>();
    k_pb<<<(N_NODES + 255) / 256, 256>>>(walk2, batch);
    k_scan<<<1, N_GRAPHS>>>();
    k_build<<<(N_NODES + 255) / 256, 256>>>(walk2, walk3, walk4);
    k_gather<<<dim3(N_GRAPHS, NSLICE), 128>>>(x);

    k_gemm<<<dim3(8, 16), 256>>>(pQ, W0, pR0);
    k_epi<<<(QELEMS + 255) / 256, 256>>>(pR0, b0, pP0, out, 0);

    k_gemm<<<dim3(8, 16), 256>>>(pP0, W1, pR1);
    k_epi<<<(QELEMS + 255) / 256, 256>>>(pR1, b1, pP1, out, 1);

    k_gemm<<<dim3(8, 16), 256>>>(pP1, W2, pR2);
    k_epi<<<(QELEMS + 255) / 256, 256>>>(pR2, b2, nullptr, out, 2);
}

// round 7
// speedup vs baseline: 3.0521x; 1.1120x over previous
#include <cuda_runtime.h>
#include <cuda_fp16.h>
#include <cstdint>

#define N_NODES  50000
#define N_GRAPHS 128
#define HID      512
#define QELEMS   (N_GRAPHS * HID)
#define NWALK    12
#define NENT     (N_NODES * NWALK)
#define NSLICE   4

// ---------------- device scratch ----------------
__device__ int   g_pb[N_NODES];
__device__ int   g_base[N_NODES];
__device__ int   g_counts[N_GRAPHS];
__device__ int   g_cursors[N_GRAPHS];
__device__ int   g_off12[N_GRAPHS];
__device__ int   g_ent[NENT];
__device__ int   g_ctr[4];
__device__ uint4 g_xh4[N_NODES * 64];     // x in fp16: 64 uint4 (= 512 halves) per row
__device__ float g_Q[QELEMS];
__device__ float g_R0[QELEMS];
__device__ float g_R1[QELEMS];
__device__ float g_R2[QELEMS];
__device__ float g_P0[QELEMS];
__device__ float g_P1[QELEMS];

// ---------------- zero scratch ----------------
__global__ void k_zero() {
    int i = blockIdx.x * blockDim.x + threadIdx.x;
    uint4 z = make_uint4(0, 0, 0, 0);
    if (i < 16384) {
        ((uint4*)g_Q)[i]  = z;
        ((uint4*)g_R0)[i] = z;
        ((uint4*)g_R1)[i] = z;
        ((uint4*)g_R2)[i] = z;
    }
    if (i < N_GRAPHS) { g_counts[i] = 0; g_cursors[i] = 0; }
    if (i < 4) g_ctr[i] = 0;
}

// ---------------- path_batch + histogram ----------------
__global__ void k_pb(const int* __restrict__ walk2, const int* __restrict__ batch) {
    int n = blockIdx.x * blockDim.x + threadIdx.x;
    if (n < N_NODES) {
        int g = batch[walk2[n]];
        g_pb[n] = g;
        atomicAdd(&g_counts[g], 1);
    }
}

// ---------------- parallel exclusive scan over 128 counts ----------------
__global__ void k_scan() {
    __shared__ int s[N_GRAPHS];
    int t = threadIdx.x;
    int v = g_counts[t];
    s[t] = v;
    __syncthreads();
    #pragma unroll
    for (int d = 1; d < N_GRAPHS; d <<= 1) {
        int u = (t >= d) ? s[t - d] : 0;
        __syncthreads();
        s[t] += u;
        __syncthreads();
    }
    g_off12[t] = (s[t] - v) * NWALK;
}

// ---------------- per-node entry base (isolates the atomic chain) ----------------
__global__ void k_base() {
    int n = blockIdx.x * blockDim.x + threadIdx.x;
    if (n < N_NODES)
        g_base[n] = g_off12[g_pb[n]] + atomicAdd(&g_cursors[g_pb[n]], NWALK);
}

// ---------------- build entry list: one thread per entry ----------------
__global__ void k_build(const int* __restrict__ w2, const int* __restrict__ w3,
                        const int* __restrict__ w4) {
    int e = blockIdx.x * blockDim.x + threadIdx.x;
    if (e >= NENT) return;
    int n = e / NWALK;
    int r = e - n * NWALK;
    int j;
    if (r < 3)      j = w2[r * N_NODES + n];
    else if (r < 7) j = w3[(r - 3) * N_NODES + n];
    else            j = w4[(r - 7) * N_NODES + n];
    g_ent[g_base[n] + r] = j;
}

// ---------------- convert x to fp16 ----------------
__global__ void k_convert(const float* __restrict__ x) {
    int i = blockIdx.x * blockDim.x + threadIdx.x;   // uint4-of-8-halves index
    if (i >= N_NODES * 64) return;
    const float4* x4 = (const float4*)x;
    float4 a = x4[2 * i];
    float4 b = x4[2 * i + 1];
    __half2 h0 = __floats2half2_rn(a.x, a.y);
    __half2 h1 = __floats2half2_rn(a.z, a.w);
    __half2 h2 = __floats2half2_rn(b.x, b.y);
    __half2 h3 = __floats2half2_rn(b.z, b.w);
    uint4 o;
    o.x = *(unsigned*)&h0; o.y = *(unsigned*)&h1;
    o.z = *(unsigned*)&h2; o.w = *(unsigned*)&h3;
    g_xh4[i] = o;
}

// ---------------- Q = A @ x : fp16 streaming gather ----------------
// grid (N_GRAPHS, NSLICE), 256 threads = 4 row-groups of 64 lanes.
// Lane c owns 8 cols (one uint4 = 8 halves); fp32 accumulation.
__global__ __launch_bounds__(256)
void k_gather() {
    const int g   = blockIdx.x;
    const int sl  = blockIdx.y;
    const int grp = threadIdx.x >> 6;
    const int c   = threadIdx.x & 63;

    const int start = g_off12[g];
    const int len   = g_counts[g] * NWALK;
    const int s0 = start + (len * sl) / NSLICE;
    const int s1 = start + (len * (sl + 1)) / NSLICE;

    float2 a0 = make_float2(0.f, 0.f), a1 = a0, a2 = a0, a3 = a0;

    int e = s0 + grp;
    for (; e + 12 < s1; e += 16) {
        int j0 = __ldg(&g_ent[e]);
        int j1 = __ldg(&g_ent[e + 4]);
        int j2 = __ldg(&g_ent[e + 8]);
        int j3 = __ldg(&g_ent[e + 12]);
        uint4 v0 = g_xh4[j0 * 64 + c];
        uint4 v1 = g_xh4[j1 * 64 + c];
        uint4 v2 = g_xh4[j2 * 64 + c];
        uint4 v3 = g_xh4[j3 * 64 + c];
        #pragma unroll
        for (int q = 0; q < 4; q++) {
            uint4 v = (q == 0) ? v0 : (q == 1) ? v1 : (q == 2) ? v2 : v3;
            float2 f0 = __half22float2(*(__half2*)&v.x);
            float2 f1 = __half22float2(*(__half2*)&v.y);
            float2 f2 = __half22float2(*(__half2*)&v.z);
            float2 f3 = __half22float2(*(__half2*)&v.w);
            a0.x += f0.x; a0.y += f0.y;
            a1.x += f1.x; a1.y += f1.y;
            a2.x += f2.x; a2.y += f2.y;
            a3.x += f3.x; a3.y += f3.y;
        }
    }
    for (; e < s1; e += 4) {
        int j = __ldg(&g_ent[e]);
        uint4 v = g_xh4[j * 64 + c];
        float2 f0 = __half22float2(*(__half2*)&v.x);
        float2 f1 = __half22float2(*(__half2*)&v.y);
        float2 f2 = __half22float2(*(__half2*)&v.z);
        float2 f3 = __half22float2(*(__half2*)&v.w);
        a0.x += f0.x; a0.y += f0.y;
        a1.x += f1.x; a1.y += f1.y;
        a2.x += f2.x; a2.y += f2.y;
        a3.x += f3.x; a3.y += f3.y;
    }

    float* Qrow = &g_Q[g * HID + c * 8];
    atomicAdd(Qrow + 0, a0.x); atomicAdd(Qrow + 1, a0.y);
    atomicAdd(Qrow + 2, a1.x); atomicAdd(Qrow + 3, a1.y);
    atomicAdd(Qrow + 4, a2.x); atomicAdd(Qrow + 5, a2.y);
    atomicAdd(Qrow + 6, a3.x); atomicAdd(Qrow + 7, a3.y);
}

// ---------------- fused layer: R = A@W (split-K atomics) ; grid-sync ; epilogue ----------------
// grid (8 nb, 16 kb) = 128 CTAs (all co-resident on 148 SMs), 256 threads.
#define GK 32
#define GN 64
__global__ __launch_bounds__(256)
void k_layer(const float* __restrict__ A, const float* __restrict__ W,
             const float* __restrict__ bias, float* __restrict__ R,
             float* __restrict__ Pout, float* __restrict__ out, int layer) {
    __shared__ float sA[GK][129];
    __shared__ float sB[GK][GN];
    int nb = blockIdx.x;
    int kb = blockIdx.y;
    int tid = threadIdx.x;

    for (int i = tid; i < 128 * GK; i += 256) {
        int m = i >> 5;
        int k = i & 31;
        sA[k][m] = A[m * HID + kb * GK + k];
    }
    for (int i = tid; i < GK * GN; i += 256) {
        int k = i >> 6;
        int cc = i & 63;
        sB[k][cc] = W[(kb * GK + k) * HID + nb * GN + cc];
    }
    __syncthreads();

    int trow = tid >> 4;
    int tcol = tid & 15;
    float acc[8][4];
    #pragma unroll
    for (int i = 0; i < 8; i++)
        #pragma unroll
        for (int jj = 0; jj < 4; jj++) acc[i][jj] = 0.f;

    #pragma unroll
    for (int k = 0; k < GK; k++) {
        float a[8], b[4];
        #pragma unroll
        for (int i = 0; i < 8; i++) a[i] = sA[k][trow * 8 + i];
        #pragma unroll
        for (int jj = 0; jj < 4; jj++) b[jj] = sB[k][tcol * 4 + jj];
        #pragma unroll
        for (int i = 0; i < 8; i++)
            #pragma unroll
            for (int jj = 0; jj < 4; jj++) acc[i][jj] += a[i] * b[jj];
    }

    #pragma unroll
    for (int i = 0; i < 8; i++)
        #pragma unroll
        for (int jj = 0; jj < 4; jj++)
            atomicAdd(&R[(trow * 8 + i) * HID + nb * GN + tcol * 4 + jj], acc[i][jj]);

    // ---- grid-wide arrival (128 CTAs, all resident) ----
    __threadfence();
    __syncthreads();
    if (tid == 0) {
        atomicAdd(&g_ctr[layer], 1);
        while (atomicAdd(&g_ctr[layer], 0) < 128) __nanosleep(64);
    }
    __syncthreads();
    __threadfence();

    // ---- epilogue: each CTA owns 512 contiguous elements ----
    int bid = blockIdx.y * 8 + blockIdx.x;
    #pragma unroll
    for (int t = tid; t < 512; t += 256) {
        int i = bid * 512 + t;
        int m = i >> 9;
        int c = i & 511;
        float cnt = (float)g_counts[m];
        float v = R[i] + 12.0f * cnt * bias[c];
        if (Pout) Pout[i] = v;
        out[m * (3 * HID) + layer * HID + c] = v / fmaxf(cnt, 1.0f);
    }
}

// ---------------- launch ----------------
extern "C" void kernel_launch(void* const* d_in, const int* in_sizes, int n_in,
                              void* d_out, int out_size) {
    const float* x     = (const float*)d_in[0];
    const int*   walk2 = (const int*)  d_in[1];
    const int*   walk3 = (const int*)  d_in[2];
    const int*   walk4 = (const int*)  d_in[3];
    const int*   batch = (const int*)  d_in[4];
    const float* W0 = (const float*)d_in[5];
    const float* b0 = (const float*)d_in[6];
    const float* W1 = (const float*)d_in[7];
    const float* b1 = (const float*)d_in[8];
    const float* W2 = (const float*)d_in[9];
    const float* b2 = (const float*)d_in[10];
    float* out = (float*)d_out;

    float *pQ, *pR0, *pR1, *pR2, *pP0, *pP1;
    cudaGetSymbolAddress((void**)&pQ,  g_Q);
    cudaGetSymbolAddress((void**)&pR0, g_R0);
    cudaGetSymbolAddress((void**)&pR1, g_R1);
    cudaGetSymbolAddress((void**)&pR2, g_R2);
    cudaGetSymbolAddress((void**)&pP0, g_P0);
    cudaGetSymbolAddress((void**)&pP1, g_P1);

    k_zero<<<64, 256>>>();
    k_pb<<<(N_NODES + 255) / 256, 256>>>(walk2, batch);
    k_convert<<<(N_NODES * 64 + 255) / 256, 256>>>(x);
    k_scan<<<1, N_GRAPHS>>>();
    k_base<<<(N_NODES + 255) / 256, 256>>>();
    k_build<<<(NENT + 255) / 256, 256>>>(walk2, walk3, walk4);
    k_gather<<<dim3(N_GRAPHS, NSLICE), 256>>>();

    k_layer<<<dim3(8, 16), 256>>>(pQ,  W0, b0, pR0, pP0, out, 0);
    k_layer<<<dim3(8, 16), 256>>>(pP0, W1, b1, pR1, pP1, out, 1);
    k_layer<<<dim3(8, 16), 256>>>(pP1, W2, b2, pR2, nullptr, out, 2);
}